// round 4
// baseline (speedup 1.0000x reference)
#include <cuda_runtime.h>
#include <cstdint>
#include <math.h>

// Problem constants
constexpr int B_  = 2;
constexpr int T_  = 2048;
constexpr int C_  = 2048;
constexpr int H_  = 16;
constexpr int HD_ = 128;
constexpr int LORA_ = 512;
constexpr int RD_ = 64;   // rope dims
constexpr int ND_ = 64;   // nope dims
constexpr int BT_ = B_ * T_;           // 4096
constexpr int CKV_W = LORA_ + RD_;     // 576
constexpr int KV_W  = H_ * ND_;        // 1024

// Scratch (static device arrays — no allocation in kernel_launch)
__device__ float g_q  [(size_t)BT_ * (H_ * HD_)];  // 4096 x 2048 (rope applied in place)
__device__ float g_ckv[(size_t)BT_ * CKV_W];       // 4096 x 576  (rope applied to last 64)
__device__ float g_kv [(size_t)BT_ * KV_W];        // 4096 x 1024
__device__ float g_y  [(size_t)BT_ * KV_W];        // 4096 x 1024 (compact attention out)

// ---------------------------------------------------------------------------
// helpers
// ---------------------------------------------------------------------------
__device__ __forceinline__ float tf32r(float x) {
    uint32_t u;
    asm("cvt.rna.tf32.f32 %0, %1;" : "=r"(u) : "f"(x));
    return __uint_as_float(u);
}

__device__ __forceinline__ void mma_m16n8k8_tf32(
    float c[4], uint32_t a0, uint32_t a1, uint32_t a2, uint32_t a3,
    uint32_t b0, uint32_t b1)
{
    asm volatile(
        "mma.sync.aligned.m16n8k8.row.col.f32.tf32.tf32.f32 "
        "{%0,%1,%2,%3}, {%4,%5,%6,%7}, {%8,%9}, {%0,%1,%2,%3};\n"
        : "+f"(c[0]), "+f"(c[1]), "+f"(c[2]), "+f"(c[3])
        : "r"(a0), "r"(a1), "r"(a2), "r"(a3), "r"(b0), "r"(b1));
}

// ---------------------------------------------------------------------------
// Generic tf32 GEMM:  C[M,N] = A[M,K] @ B[K,N]   (row-major, fp32 in/out)
// Requires M % 128 == 0, K % 32 == 0, N % 4 == 0 (N tail handled by guards).
// MAPB: map B row index k -> (k>>6)*128 + (k&63) (compact-y @ Wo).
// ---------------------------------------------------------------------------
constexpr int GBM = 128, GBN = 128, GBK = 32;
constexpr int ALD = GBK + 4;   // 36  -> conflict-free A fragment loads
constexpr int BLD = GBN + 8;   // 136 -> conflict-free B fragment loads

template<bool MAPB>
__global__ __launch_bounds__(256)
void gemm_tf32(const float* __restrict__ A, const float* __restrict__ B,
               float* __restrict__ C, int M, int N, int K,
               int lda, int ldb, int ldc)
{
    __shared__ float As[GBM * ALD];
    __shared__ float Bs[GBK * BLD];

    const int tid  = threadIdx.x;
    const int warp = tid >> 5, lane = tid & 31;
    const int wm = warp >> 2;       // 0..1 -> 64-row slab
    const int wn = warp & 3;        // 0..3 -> 32-col slab
    const int g  = lane >> 2, t4 = lane & 3;
    const int bm0 = blockIdx.y * GBM;
    const int bn0 = blockIdx.x * GBN;

    float c[4][4][4];
#pragma unroll
    for (int mi = 0; mi < 4; mi++)
#pragma unroll
        for (int ni = 0; ni < 4; ni++)
#pragma unroll
            for (int r = 0; r < 4; r++) c[mi][ni][r] = 0.f;

    for (int k0 = 0; k0 < K; k0 += GBK) {
        __syncthreads();
        // A tile: 128x32 (row-major gmem) -> As[m][k]
#pragma unroll
        for (int i = 0; i < 4; i++) {
            int f = tid + i * 256;          // 0..1023 float4s
            int m = f >> 3;
            int kk = (f & 7) << 2;
            const float4 v = *reinterpret_cast<const float4*>(
                &A[(size_t)(bm0 + m) * lda + (k0 + kk)]);
            float* d = &As[m * ALD + kk];
            d[0] = tf32r(v.x); d[1] = tf32r(v.y);
            d[2] = tf32r(v.z); d[3] = tf32r(v.w);
        }
        // B tile: 32x128 -> Bs[k][n]
#pragma unroll
        for (int i = 0; i < 4; i++) {
            int f = tid + i * 256;
            int kk = f >> 5;
            int n  = (f & 31) << 2;
            int col = bn0 + n;
            float4 v = make_float4(0.f, 0.f, 0.f, 0.f);
            if (col < N) {
                int row = k0 + kk;
                if (MAPB) row = ((row >> 6) << 7) | (row & 63);
                v = *reinterpret_cast<const float4*>(&B[(size_t)row * ldb + col]);
            }
            float* d = &Bs[kk * BLD + n];
            d[0] = tf32r(v.x); d[1] = tf32r(v.y);
            d[2] = tf32r(v.z); d[3] = tf32r(v.w);
        }
        __syncthreads();

#pragma unroll
        for (int kk = 0; kk < GBK; kk += 8) {
            uint32_t a[4][4], bb[4][2];
#pragma unroll
            for (int mi = 0; mi < 4; mi++) {
                const float* base = &As[(wm * 64 + mi * 16) * ALD + kk + t4];
                a[mi][0] = __float_as_uint(base[(size_t)g * ALD]);
                a[mi][1] = __float_as_uint(base[(size_t)(g + 8) * ALD]);
                a[mi][2] = __float_as_uint(base[(size_t)g * ALD + 4]);
                a[mi][3] = __float_as_uint(base[(size_t)(g + 8) * ALD + 4]);
            }
#pragma unroll
            for (int ni = 0; ni < 4; ni++) {
                const float* base = &Bs[(kk + t4) * BLD + wn * 32 + ni * 8 + g];
                bb[ni][0] = __float_as_uint(base[0]);
                bb[ni][1] = __float_as_uint(base[4 * BLD]);
            }
#pragma unroll
            for (int mi = 0; mi < 4; mi++)
#pragma unroll
                for (int ni = 0; ni < 4; ni++)
                    mma_m16n8k8_tf32(c[mi][ni],
                                     a[mi][0], a[mi][1], a[mi][2], a[mi][3],
                                     bb[ni][0], bb[ni][1]);
        }
    }

    // epilogue (N guarded; N is even so col+1 safe when col < N)
#pragma unroll
    for (int mi = 0; mi < 4; mi++) {
#pragma unroll
        for (int ni = 0; ni < 4; ni++) {
            int row = bm0 + wm * 64 + mi * 16 + g;
            int col = bn0 + wn * 32 + ni * 8 + 2 * t4;
            if (col < N) {
                C[(size_t)row * ldc + col]       = c[mi][ni][0];
                C[(size_t)row * ldc + col + 1]   = c[mi][ni][1];
                C[(size_t)(row + 8) * ldc + col]     = c[mi][ni][2];
                C[(size_t)(row + 8) * ldc + col + 1] = c[mi][ni][3];
            }
        }
    }
}

// ---------------------------------------------------------------------------
// RoPE (in place). Angle reduced mod 2*pi in double, then fast sincos.
// ---------------------------------------------------------------------------
__device__ __forceinline__ void rope_pair(float* p, int t, int i) {
    // freq = theta^(-i/32), theta = 1e5; ln(1e5) = 11.512925464970229
    double freq = exp((double)i * (-11.512925464970229 / 32.0));
    double ang  = (double)t * freq;
    ang -= floor(ang * 0.15915494309189535) * 6.283185307179586;
    float sa, ca;
    __sincosf((float)ang, &sa, &ca);
    float x0 = p[0], x1 = p[1];
    p[0] = x0 * ca - x1 * sa;
    p[1] = x0 * sa + x1 * ca;
}

__global__ void rope_q_kernel(float* __restrict__ q) {
    int idx = blockIdx.x * blockDim.x + threadIdx.x;   // over BT*H*32
    if (idx >= BT_ * H_ * (RD_ / 2)) return;
    int i  = idx & 31;
    int h  = (idx >> 5) & (H_ - 1);
    int bt = idx >> 9;
    int t  = bt & (T_ - 1);
    rope_pair(q + (size_t)bt * (H_ * HD_) + h * HD_ + ND_ + 2 * i, t, i);
}

__global__ void rope_k_kernel(float* __restrict__ ckv) {
    int idx = blockIdx.x * blockDim.x + threadIdx.x;   // over BT*32
    if (idx >= BT_ * (RD_ / 2)) return;
    int i  = idx & 31;
    int bt = idx >> 5;
    int t  = bt & (T_ - 1);
    rope_pair(ckv + (size_t)bt * CKV_W + LORA_ + 2 * i, t, i);
}

// ---------------------------------------------------------------------------
// Flash attention (causal), tf32 mma.
//   Q tile: 64 rows x 128 dims (rope already applied)
//   K tile: 64 keys x 128 dims = [kv(h) | roped k_rope(shared)]
//   V tile: 64 keys x 64 dims  = kv(h)
//   Output: y[bt][h*64 + d]  (only nonzero 64 dims per head)
// 4 warps; each warp owns 16 q rows. P re-fragmented through smem.
// ---------------------------------------------------------------------------
constexpr int QLD = 136, KLD = 136, VLD = 72, PLD = 72;
constexpr int ATTN_SMEM = (64 * QLD + 64 * KLD + 64 * VLD + 64 * PLD) * 4; // 106496 B

__global__ __launch_bounds__(128)
void mla_attn_kernel(const float* __restrict__ qb, const float* __restrict__ kvb,
                     const float* __restrict__ ckv, float* __restrict__ yb)
{
    extern __shared__ float sm[];
    float* Qs = sm;
    float* Ks = Qs + 64 * QLD;
    float* Vs = Ks + 64 * KLD;
    float* Ps = Vs + 64 * VLD;

    const int qt = (int)gridDim.x - 1 - (int)blockIdx.x;  // heavy tiles first
    const int h  = blockIdx.y;
    const int b  = blockIdx.z;
    const int tid  = threadIdx.x;
    const int warp = tid >> 5, lane = tid & 31;
    const int g = lane >> 2, t4 = lane & 3;

    // load Q tile (tf32-rounded)
#pragma unroll
    for (int i = 0; i < 16; i++) {
        int f = tid + i * 128;
        int r = f >> 5;
        int d = (f & 31) << 2;
        const float4 v = *reinterpret_cast<const float4*>(
            &qb[(size_t)(b * T_ + qt * 64 + r) * (H_ * HD_) + h * HD_ + d]);
        float* dst = &Qs[r * QLD + d];
        dst[0] = tf32r(v.x); dst[1] = tf32r(v.y);
        dst[2] = tf32r(v.z); dst[3] = tf32r(v.w);
    }

    float o[8][4];
#pragma unroll
    for (int ni = 0; ni < 8; ni++)
#pragma unroll
        for (int r = 0; r < 4; r++) o[ni][r] = 0.f;
    float mrow[2] = {-1e30f, -1e30f};
    float lrow[2] = {0.f, 0.f};

    for (int kt = 0; kt <= qt; kt++) {
        __syncthreads();
        // K tile: dims 0..63 from kv (per head), dims 64..127 from roped k_rope
#pragma unroll
        for (int i = 0; i < 16; i++) {
            int f = tid + i * 128;
            int r = f >> 5;
            int d = (f & 31) << 2;
            size_t srow = (size_t)(b * T_ + kt * 64 + r);
            float4 v;
            if (d < 64)
                v = *reinterpret_cast<const float4*>(&kvb[srow * KV_W + h * ND_ + d]);
            else
                v = *reinterpret_cast<const float4*>(&ckv[srow * CKV_W + LORA_ + (d - 64)]);
            float* dst = &Ks[r * KLD + d];
            dst[0] = tf32r(v.x); dst[1] = tf32r(v.y);
            dst[2] = tf32r(v.z); dst[3] = tf32r(v.w);
        }
        // V tile
#pragma unroll
        for (int i = 0; i < 8; i++) {
            int f = tid + i * 128;
            int r = f >> 4;
            int d = (f & 15) << 2;
            const float4 v = *reinterpret_cast<const float4*>(
                &kvb[(size_t)(b * T_ + kt * 64 + r) * KV_W + h * ND_ + d]);
            float* dst = &Vs[r * VLD + d];
            dst[0] = tf32r(v.x); dst[1] = tf32r(v.y);
            dst[2] = tf32r(v.z); dst[3] = tf32r(v.w);
        }
        __syncthreads();

        // S = Q @ K^T  (warp rows = warp*16 .. +15, all 64 key cols)
        float s[8][4];
#pragma unroll
        for (int ni = 0; ni < 8; ni++)
#pragma unroll
            for (int r = 0; r < 4; r++) s[ni][r] = 0.f;

#pragma unroll
        for (int kk = 0; kk < 128; kk += 8) {
            const float* qbase = &Qs[(warp * 16) * QLD + kk + t4];
            uint32_t a0 = __float_as_uint(qbase[(size_t)g * QLD]);
            uint32_t a1 = __float_as_uint(qbase[(size_t)(g + 8) * QLD]);
            uint32_t a2 = __float_as_uint(qbase[(size_t)g * QLD + 4]);
            uint32_t a3 = __float_as_uint(qbase[(size_t)(g + 8) * QLD + 4]);
#pragma unroll
            for (int ni = 0; ni < 8; ni++) {
                const float* kbase = &Ks[(ni * 8 + g) * KLD + kk + t4];
                uint32_t b0 = __float_as_uint(kbase[0]);
                uint32_t b1 = __float_as_uint(kbase[4]);
                mma_m16n8k8_tf32(s[ni], a0, a1, a2, a3, b0, b1);
            }
        }

        // scale + causal mask (diagonal tile only) + online softmax
        const float sc = 0.08838834764831843f;   // 1/sqrt(128)
        const bool diag = (kt == qt);
        float rmax[2] = {-1e30f, -1e30f};
#pragma unroll
        for (int ni = 0; ni < 8; ni++) {
#pragma unroll
            for (int r = 0; r < 4; r++) {
                float v = s[ni][r] * sc;
                if (diag) {
                    int rowl = warp * 16 + g + ((r >> 1) << 3);
                    int coll = ni * 8 + 2 * t4 + (r & 1);
                    if (coll > rowl) v = -1e30f;
                }
                s[ni][r] = v;
                rmax[r >> 1] = fmaxf(rmax[r >> 1], v);
            }
        }
#pragma unroll
        for (int j = 0; j < 2; j++) {
            rmax[j] = fmaxf(rmax[j], __shfl_xor_sync(0xffffffffu, rmax[j], 1));
            rmax[j] = fmaxf(rmax[j], __shfl_xor_sync(0xffffffffu, rmax[j], 2));
        }
        float mnew[2], alpha[2], rsum[2] = {0.f, 0.f};
#pragma unroll
        for (int j = 0; j < 2; j++) {
            mnew[j]  = fmaxf(mrow[j], rmax[j]);
            alpha[j] = __expf(mrow[j] - mnew[j]);
        }
        // p = exp(s - mnew); write to Ps in A-fragment-friendly layout
#pragma unroll
        for (int ni = 0; ni < 8; ni++) {
#pragma unroll
            for (int r = 0; r < 4; r++) {
                int half = r >> 1;
                float p = __expf(s[ni][r] - mnew[half]);
                rsum[half] += p;
                Ps[(warp * 16 + g + (half << 3)) * PLD + ni * 8 + 2 * t4 + (r & 1)]
                    = tf32r(p);
            }
        }
#pragma unroll
        for (int j = 0; j < 2; j++) {
            rsum[j] += __shfl_xor_sync(0xffffffffu, rsum[j], 1);
            rsum[j] += __shfl_xor_sync(0xffffffffu, rsum[j], 2);
            lrow[j] = lrow[j] * alpha[j] + rsum[j];
            mrow[j] = mnew[j];
        }
#pragma unroll
        for (int ni = 0; ni < 8; ni++)
#pragma unroll
            for (int r = 0; r < 4; r++) o[ni][r] *= alpha[r >> 1];

        __syncwarp();   // Ps visible within warp (no cross-warp sharing of P)

        // O += P @ V
#pragma unroll
        for (int kk = 0; kk < 64; kk += 8) {
            const float* pbase = &Ps[(warp * 16) * PLD + kk + t4];
            uint32_t a0 = __float_as_uint(pbase[(size_t)g * PLD]);
            uint32_t a1 = __float_as_uint(pbase[(size_t)(g + 8) * PLD]);
            uint32_t a2 = __float_as_uint(pbase[(size_t)g * PLD + 4]);
            uint32_t a3 = __float_as_uint(pbase[(size_t)(g + 8) * PLD + 4]);
#pragma unroll
            for (int ni = 0; ni < 8; ni++) {
                const float* vb = &Vs[(kk + t4) * VLD + ni * 8 + g];
                uint32_t b0 = __float_as_uint(vb[0]);
                uint32_t b1 = __float_as_uint(vb[4 * VLD]);
                mma_m16n8k8_tf32(o[ni], a0, a1, a2, a3, b0, b1);
            }
        }
    }

    // finalize: divide by row sum and store compact y (64 dims/head)
    const float inv0 = 1.f / lrow[0];
    const float inv1 = 1.f / lrow[1];
#pragma unroll
    for (int ni = 0; ni < 8; ni++) {
        int col = ni * 8 + 2 * t4;
        size_t row0 = (size_t)(b * T_ + qt * 64 + warp * 16 + g);
        float* y0 = &yb[row0 * KV_W + h * ND_ + col];
        y0[0] = o[ni][0] * inv0;
        y0[1] = o[ni][1] * inv0;
        float* y1 = y0 + (size_t)8 * KV_W;
        y1[0] = o[ni][2] * inv1;
        y1[1] = o[ni][3] * inv1;
    }
}

// ---------------------------------------------------------------------------
// launch
// ---------------------------------------------------------------------------
extern "C" void kernel_launch(void* const* d_in, const int* in_sizes, int n_in,
                              void* d_out, int out_size)
{
    (void)in_sizes; (void)n_in; (void)out_size;
    const float* x    = (const float*)d_in[0];
    const float* Wq   = (const float*)d_in[1];
    const float* Wkva = (const float*)d_in[2];
    const float* Wkvb = (const float*)d_in[3];
    const float* Wo   = (const float*)d_in[4];
    float* out = (float*)d_out;

    float *qb, *ckv, *kv, *yb;
    cudaGetSymbolAddress((void**)&qb,  g_q);
    cudaGetSymbolAddress((void**)&ckv, g_ckv);
    cudaGetSymbolAddress((void**)&kv,  g_kv);
    cudaGetSymbolAddress((void**)&yb,  g_y);

    cudaFuncSetAttribute((const void*)mla_attn_kernel,
                         cudaFuncAttributeMaxDynamicSharedMemorySize, ATTN_SMEM);

    // 1) q = x @ Wq                       (4096 x 2048 x 2048)
    gemm_tf32<false><<<dim3(2048 / GBN, BT_ / GBM), 256>>>(
        x, Wq, qb, BT_, 2048, 2048, 2048, 2048, 2048);

    // 2) ckv = x @ Wkva                   (4096 x 576 x 2048)
    gemm_tf32<false><<<dim3((CKV_W + GBN - 1) / GBN, BT_ / GBM), 256>>>(
        x, Wkva, ckv, BT_, CKV_W, 2048, 2048, CKV_W, CKV_W);

    // 3) RoPE (in place)
    rope_q_kernel<<<(BT_ * H_ * (RD_ / 2) + 255) / 256, 256>>>(qb);
    rope_k_kernel<<<(BT_ * (RD_ / 2) + 255) / 256, 256>>>(ckv);

    // 4) kv = ckv[:, :512] @ Wkvb         (4096 x 1024 x 512), lda = 576
    gemm_tf32<false><<<dim3(KV_W / GBN, BT_ / GBM), 256>>>(
        ckv, Wkvb, kv, BT_, KV_W, LORA_, CKV_W, KV_W, KV_W);

    // 5) causal flash attention -> compact y (4096 x 1024)
    mla_attn_kernel<<<dim3(T_ / 64, H_, B_), 128, ATTN_SMEM>>>(qb, kv, ckv, yb);

    // 6) out = y_compact @ Wo[row-mapped] (4096 x 2048 x 1024)
    gemm_tf32<true><<<dim3(2048 / GBN, BT_ / GBM), 256>>>(
        yb, Wo, out, BT_, 2048, KV_W, KV_W, 2048, 2048);
}

// round 5
// speedup vs baseline: 1.0040x; 1.0040x over previous
#include <cuda_runtime.h>
#include <cstdint>
#include <math.h>

// Problem constants
constexpr int B_  = 2;
constexpr int T_  = 2048;
constexpr int C_  = 2048;
constexpr int H_  = 16;
constexpr int HD_ = 128;
constexpr int LORA_ = 512;
constexpr int RD_ = 64;   // rope dims
constexpr int ND_ = 64;   // nope dims
constexpr int BT_ = B_ * T_;           // 4096
constexpr int CKV_W = LORA_ + RD_;     // 576
constexpr int KV_W  = H_ * ND_;        // 1024

// Scratch (static device arrays — no allocation in kernel_launch)
__device__ float g_q  [(size_t)BT_ * (H_ * HD_)];  // 4096 x 2048 (rope applied in place)
__device__ float g_ckv[(size_t)BT_ * CKV_W];       // 4096 x 576  (rope applied to last 64)
__device__ float g_kv [(size_t)BT_ * KV_W];        // 4096 x 1024
__device__ float g_y  [(size_t)BT_ * KV_W];        // 4096 x 1024 (compact attention out)

// ---------------------------------------------------------------------------
// helpers
// ---------------------------------------------------------------------------
__device__ __forceinline__ float tf32r(float x) {
    uint32_t u;
    asm("cvt.rna.tf32.f32 %0, %1;" : "=r"(u) : "f"(x));
    return __uint_as_float(u);
}
__device__ __forceinline__ uint32_t tf32u(float x) {
    uint32_t u;
    asm("cvt.rna.tf32.f32 %0, %1;" : "=r"(u) : "f"(x));
    return u;
}

__device__ __forceinline__ void mma_m16n8k8_tf32(
    float c[4], uint32_t a0, uint32_t a1, uint32_t a2, uint32_t a3,
    uint32_t b0, uint32_t b1)
{
    asm volatile(
        "mma.sync.aligned.m16n8k8.row.col.f32.tf32.tf32.f32 "
        "{%0,%1,%2,%3}, {%4,%5,%6,%7}, {%8,%9}, {%0,%1,%2,%3};\n"
        : "+f"(c[0]), "+f"(c[1]), "+f"(c[2]), "+f"(c[3])
        : "r"(a0), "r"(a1), "r"(a2), "r"(a3), "r"(b0), "r"(b1));
}

__device__ __forceinline__ uint32_t smem_u32(const void* p) {
    return (uint32_t)__cvta_generic_to_shared(p);
}

// ---------------------------------------------------------------------------
// Pipelined tf32 GEMM:  C[M,N] = A[M,K] @ B[K,N]   (row-major, fp32 in/out)
// 3-stage cp.async pipeline. Requires M%128==0, K%32==0, K/32>=2.
// MAPB: map B row index k -> (k>>6)*128 + (k&63)  (compact-y @ Wo).
// ---------------------------------------------------------------------------
constexpr int GBM = 128, GBN = 128, GBK = 32;
constexpr int ALD = GBK + 4;   // 36  floats (row stride 144B, 16B aligned)
constexpr int BLD = GBN + 8;   // 136 floats (row stride 544B, 16B aligned)
constexpr int G_ASZ = GBM * ALD;          // 4608 floats
constexpr int G_BSZ = GBK * BLD;          // 4352 floats
constexpr int G_STG = G_ASZ + G_BSZ;      // 8960 floats / stage
constexpr int GEMM_SMEM = 3 * G_STG * 4;  // 107520 bytes

template<bool MAPB>
__global__ __launch_bounds__(256)
void gemm_tf32(const float* __restrict__ A, const float* __restrict__ B,
               float* __restrict__ C, int M, int N, int K,
               int lda, int ldb, int ldc)
{
    extern __shared__ float smem[];

    const int tid  = threadIdx.x;
    const int warp = tid >> 5, lane = tid & 31;
    const int wm = warp >> 2;       // 0..1 -> 64-row slab
    const int wn = warp & 3;        // 0..3 -> 32-col slab
    const int g  = lane >> 2, t4 = lane & 3;
    const int bm0 = blockIdx.y * GBM;
    const int bn0 = blockIdx.x * GBN;
    const int nt  = K / GBK;

    auto load_stage = [&](int it, int s) {
        const int k0 = it * GBK;
        float* As = smem + s * G_STG;
        float* Bs = As + G_ASZ;
#pragma unroll
        for (int i = 0; i < 4; i++) {
            int f = tid + i * 256;          // 0..1023 float4 slots
            int m = f >> 3;
            int kk = (f & 7) << 2;
            uint32_t dst = smem_u32(&As[m * ALD + kk]);
            const float* src = &A[(size_t)(bm0 + m) * lda + (k0 + kk)];
            asm volatile("cp.async.cg.shared.global [%0], [%1], 16;\n"
                         :: "r"(dst), "l"(src));
        }
#pragma unroll
        for (int i = 0; i < 4; i++) {
            int f = tid + i * 256;
            int kk = f >> 5;
            int n  = (f & 31) << 2;
            int col = bn0 + n;
            int row = k0 + kk;
            if (MAPB) row = ((row >> 6) << 7) | (row & 63);
            const float* src = &B[(size_t)row * ldb + (col < N ? col : 0)];
            uint32_t dst = smem_u32(&Bs[kk * BLD + n]);
            int sz = (col < N) ? 16 : 0;    // zero-fill out-of-range columns
            asm volatile("cp.async.cg.shared.global [%0], [%1], 16, %2;\n"
                         :: "r"(dst), "l"(src), "r"(sz));
        }
        asm volatile("cp.async.commit_group;\n" ::: "memory");
    };

    float c[4][4][4];
#pragma unroll
    for (int mi = 0; mi < 4; mi++)
#pragma unroll
        for (int ni = 0; ni < 4; ni++)
#pragma unroll
            for (int r = 0; r < 4; r++) c[mi][ni][r] = 0.f;

    load_stage(0, 0);
    load_stage(1, 1);

    for (int it = 0; it < nt; it++) {
        // all groups except the most recent one are retired -> tile `it` ready
        asm volatile("cp.async.wait_group 1;\n" ::: "memory");
        __syncthreads();

        // keep exactly one commit per iteration (in-order retirement)
        if (it + 2 < nt) load_stage(it + 2, (it + 2) % 3);
        else asm volatile("cp.async.commit_group;\n" ::: "memory");

        const float* As = smem + (it % 3) * G_STG;
        const float* Bs = As + G_ASZ;

#pragma unroll
        for (int kk = 0; kk < GBK; kk += 8) {
            uint32_t a[4][4], bb[4][2];
#pragma unroll
            for (int mi = 0; mi < 4; mi++) {
                const float* base = &As[(wm * 64 + mi * 16) * ALD + kk + t4];
                a[mi][0] = tf32u(base[(size_t)g * ALD]);
                a[mi][1] = tf32u(base[(size_t)(g + 8) * ALD]);
                a[mi][2] = tf32u(base[(size_t)g * ALD + 4]);
                a[mi][3] = tf32u(base[(size_t)(g + 8) * ALD + 4]);
            }
#pragma unroll
            for (int ni = 0; ni < 4; ni++) {
                const float* base = &Bs[(kk + t4) * BLD + wn * 32 + ni * 8 + g];
                bb[ni][0] = tf32u(base[0]);
                bb[ni][1] = tf32u(base[4 * BLD]);
            }
#pragma unroll
            for (int mi = 0; mi < 4; mi++)
#pragma unroll
                for (int ni = 0; ni < 4; ni++)
                    mma_m16n8k8_tf32(c[mi][ni],
                                     a[mi][0], a[mi][1], a[mi][2], a[mi][3],
                                     bb[ni][0], bb[ni][1]);
        }
        __syncthreads();   // stage reuse barrier (3-stage: next load hits it%3)
    }

    // epilogue (N guarded; N is even so col+1 safe when col < N)
#pragma unroll
    for (int mi = 0; mi < 4; mi++) {
#pragma unroll
        for (int ni = 0; ni < 4; ni++) {
            int row = bm0 + wm * 64 + mi * 16 + g;
            int col = bn0 + wn * 32 + ni * 8 + 2 * t4;
            if (col < N) {
                C[(size_t)row * ldc + col]           = c[mi][ni][0];
                C[(size_t)row * ldc + col + 1]       = c[mi][ni][1];
                C[(size_t)(row + 8) * ldc + col]     = c[mi][ni][2];
                C[(size_t)(row + 8) * ldc + col + 1] = c[mi][ni][3];
            }
        }
    }
}

// ---------------------------------------------------------------------------
// RoPE (in place). Angle reduced mod 2*pi in double, then fast sincos.
// ---------------------------------------------------------------------------
__device__ __forceinline__ void rope_pair(float* p, int t, int i) {
    double freq = exp((double)i * (-11.512925464970229 / 32.0));
    double ang  = (double)t * freq;
    ang -= floor(ang * 0.15915494309189535) * 6.283185307179586;
    float sa, ca;
    __sincosf((float)ang, &sa, &ca);
    float x0 = p[0], x1 = p[1];
    p[0] = x0 * ca - x1 * sa;
    p[1] = x0 * sa + x1 * ca;
}

__global__ void rope_q_kernel(float* __restrict__ q) {
    int idx = blockIdx.x * blockDim.x + threadIdx.x;   // over BT*H*32
    if (idx >= BT_ * H_ * (RD_ / 2)) return;
    int i  = idx & 31;
    int h  = (idx >> 5) & (H_ - 1);
    int bt = idx >> 9;
    int t  = bt & (T_ - 1);
    rope_pair(q + (size_t)bt * (H_ * HD_) + h * HD_ + ND_ + 2 * i, t, i);
}

__global__ void rope_k_kernel(float* __restrict__ ckv) {
    int idx = blockIdx.x * blockDim.x + threadIdx.x;   // over BT*32
    if (idx >= BT_ * (RD_ / 2)) return;
    int i  = idx & 31;
    int bt = idx >> 5;
    int t  = bt & (T_ - 1);
    rope_pair(ckv + (size_t)bt * CKV_W + LORA_ + 2 * i, t, i);
}

// ---------------------------------------------------------------------------
// Flash attention (causal), tf32 mma.
//   Q tile: 64 rows x 128 dims (rope already applied)
//   K tile: 64 keys x 128 dims = [kv(h) | roped k_rope(shared)]
//   V tile: 64 keys x 64 dims  = kv(h)
//   Output: y[bt][h*64 + d]  (only nonzero 64 dims per head)
// 4 warps; each warp owns 16 q rows. P re-fragmented through smem.
// ---------------------------------------------------------------------------
constexpr int QLD = 136, KLD = 136, VLD = 72, PLD = 72;
constexpr int ATTN_SMEM = (64 * QLD + 64 * KLD + 64 * VLD + 64 * PLD) * 4; // 106496 B

__global__ __launch_bounds__(128)
void mla_attn_kernel(const float* __restrict__ qb, const float* __restrict__ kvb,
                     const float* __restrict__ ckv, float* __restrict__ yb)
{
    extern __shared__ float sm[];
    float* Qs = sm;
    float* Ks = Qs + 64 * QLD;
    float* Vs = Ks + 64 * KLD;
    float* Ps = Vs + 64 * VLD;

    const int qt = (int)gridDim.x - 1 - (int)blockIdx.x;  // heavy tiles first
    const int h  = blockIdx.y;
    const int b  = blockIdx.z;
    const int tid  = threadIdx.x;
    const int warp = tid >> 5, lane = tid & 31;
    const int g = lane >> 2, t4 = lane & 3;

    // load Q tile (tf32-rounded)
#pragma unroll
    for (int i = 0; i < 16; i++) {
        int f = tid + i * 128;
        int r = f >> 5;
        int d = (f & 31) << 2;
        const float4 v = *reinterpret_cast<const float4*>(
            &qb[(size_t)(b * T_ + qt * 64 + r) * (H_ * HD_) + h * HD_ + d]);
        float* dst = &Qs[r * QLD + d];
        dst[0] = tf32r(v.x); dst[1] = tf32r(v.y);
        dst[2] = tf32r(v.z); dst[3] = tf32r(v.w);
    }

    float o[8][4];
#pragma unroll
    for (int ni = 0; ni < 8; ni++)
#pragma unroll
        for (int r = 0; r < 4; r++) o[ni][r] = 0.f;
    float mrow[2] = {-1e30f, -1e30f};
    float lrow[2] = {0.f, 0.f};

    for (int kt = 0; kt <= qt; kt++) {
        __syncthreads();
        // K tile: dims 0..63 from kv (per head), dims 64..127 from roped k_rope
#pragma unroll
        for (int i = 0; i < 16; i++) {
            int f = tid + i * 128;
            int r = f >> 5;
            int d = (f & 31) << 2;
            size_t srow = (size_t)(b * T_ + kt * 64 + r);
            float4 v;
            if (d < 64)
                v = *reinterpret_cast<const float4*>(&kvb[srow * KV_W + h * ND_ + d]);
            else
                v = *reinterpret_cast<const float4*>(&ckv[srow * CKV_W + LORA_ + (d - 64)]);
            float* dst = &Ks[r * KLD + d];
            dst[0] = tf32r(v.x); dst[1] = tf32r(v.y);
            dst[2] = tf32r(v.z); dst[3] = tf32r(v.w);
        }
        // V tile
#pragma unroll
        for (int i = 0; i < 8; i++) {
            int f = tid + i * 128;
            int r = f >> 4;
            int d = (f & 15) << 2;
            const float4 v = *reinterpret_cast<const float4*>(
                &kvb[(size_t)(b * T_ + kt * 64 + r) * KV_W + h * ND_ + d]);
            float* dst = &Vs[r * VLD + d];
            dst[0] = tf32r(v.x); dst[1] = tf32r(v.y);
            dst[2] = tf32r(v.z); dst[3] = tf32r(v.w);
        }
        __syncthreads();

        // S = Q @ K^T
        float s[8][4];
#pragma unroll
        for (int ni = 0; ni < 8; ni++)
#pragma unroll
            for (int r = 0; r < 4; r++) s[ni][r] = 0.f;

#pragma unroll
        for (int kk = 0; kk < 128; kk += 8) {
            const float* qbase = &Qs[(warp * 16) * QLD + kk + t4];
            uint32_t a0 = __float_as_uint(qbase[(size_t)g * QLD]);
            uint32_t a1 = __float_as_uint(qbase[(size_t)(g + 8) * QLD]);
            uint32_t a2 = __float_as_uint(qbase[(size_t)g * QLD + 4]);
            uint32_t a3 = __float_as_uint(qbase[(size_t)(g + 8) * QLD + 4]);
#pragma unroll
            for (int ni = 0; ni < 8; ni++) {
                const float* kbase = &Ks[(ni * 8 + g) * KLD + kk + t4];
                uint32_t b0 = __float_as_uint(kbase[0]);
                uint32_t b1 = __float_as_uint(kbase[4]);
                mma_m16n8k8_tf32(s[ni], a0, a1, a2, a3, b0, b1);
            }
        }

        // scale + causal mask (diagonal tile only) + online softmax
        const float sc = 0.08838834764831843f;   // 1/sqrt(128)
        const bool diag = (kt == qt);
        float rmax[2] = {-1e30f, -1e30f};
#pragma unroll
        for (int ni = 0; ni < 8; ni++) {
#pragma unroll
            for (int r = 0; r < 4; r++) {
                float v = s[ni][r] * sc;
                if (diag) {
                    int rowl = warp * 16 + g + ((r >> 1) << 3);
                    int coll = ni * 8 + 2 * t4 + (r & 1);
                    if (coll > rowl) v = -1e30f;
                }
                s[ni][r] = v;
                rmax[r >> 1] = fmaxf(rmax[r >> 1], v);
            }
        }
#pragma unroll
        for (int j = 0; j < 2; j++) {
            rmax[j] = fmaxf(rmax[j], __shfl_xor_sync(0xffffffffu, rmax[j], 1));
            rmax[j] = fmaxf(rmax[j], __shfl_xor_sync(0xffffffffu, rmax[j], 2));
        }
        float mnew[2], alpha[2], rsum[2] = {0.f, 0.f};
#pragma unroll
        for (int j = 0; j < 2; j++) {
            mnew[j]  = fmaxf(mrow[j], rmax[j]);
            alpha[j] = __expf(mrow[j] - mnew[j]);
        }
#pragma unroll
        for (int ni = 0; ni < 8; ni++) {
#pragma unroll
            for (int r = 0; r < 4; r++) {
                int half = r >> 1;
                float p = __expf(s[ni][r] - mnew[half]);
                rsum[half] += p;
                Ps[(warp * 16 + g + (half << 3)) * PLD + ni * 8 + 2 * t4 + (r & 1)]
                    = tf32r(p);
            }
        }
#pragma unroll
        for (int j = 0; j < 2; j++) {
            rsum[j] += __shfl_xor_sync(0xffffffffu, rsum[j], 1);
            rsum[j] += __shfl_xor_sync(0xffffffffu, rsum[j], 2);
            lrow[j] = lrow[j] * alpha[j] + rsum[j];
            mrow[j] = mnew[j];
        }
#pragma unroll
        for (int ni = 0; ni < 8; ni++)
#pragma unroll
            for (int r = 0; r < 4; r++) o[ni][r] *= alpha[r >> 1];

        __syncwarp();   // Ps visible within warp (no cross-warp sharing of P)

        // O += P @ V
#pragma unroll
        for (int kk = 0; kk < 64; kk += 8) {
            const float* pbase = &Ps[(warp * 16) * PLD + kk + t4];
            uint32_t a0 = __float_as_uint(pbase[(size_t)g * PLD]);
            uint32_t a1 = __float_as_uint(pbase[(size_t)(g + 8) * PLD]);
            uint32_t a2 = __float_as_uint(pbase[(size_t)g * PLD + 4]);
            uint32_t a3 = __float_as_uint(pbase[(size_t)(g + 8) * PLD + 4]);
#pragma unroll
            for (int ni = 0; ni < 8; ni++) {
                const float* vb = &Vs[(kk + t4) * VLD + ni * 8 + g];
                uint32_t b0 = __float_as_uint(vb[0]);
                uint32_t b1 = __float_as_uint(vb[4 * VLD]);
                mma_m16n8k8_tf32(o[ni], a0, a1, a2, a3, b0, b1);
            }
        }
    }

    // finalize: divide by row sum and store compact y (64 dims/head)
    const float inv0 = 1.f / lrow[0];
    const float inv1 = 1.f / lrow[1];
#pragma unroll
    for (int ni = 0; ni < 8; ni++) {
        int col = ni * 8 + 2 * t4;
        size_t row0 = (size_t)(b * T_ + qt * 64 + warp * 16 + g);
        float* y0 = &yb[row0 * KV_W + h * ND_ + col];
        y0[0] = o[ni][0] * inv0;
        y0[1] = o[ni][1] * inv0;
        float* y1 = y0 + (size_t)8 * KV_W;
        y1[0] = o[ni][2] * inv1;
        y1[1] = o[ni][3] * inv1;
    }
}

// ---------------------------------------------------------------------------
// launch
// ---------------------------------------------------------------------------
extern "C" void kernel_launch(void* const* d_in, const int* in_sizes, int n_in,
                              void* d_out, int out_size)
{
    (void)in_sizes; (void)n_in; (void)out_size;
    const float* x    = (const float*)d_in[0];
    const float* Wq   = (const float*)d_in[1];
    const float* Wkva = (const float*)d_in[2];
    const float* Wkvb = (const float*)d_in[3];
    const float* Wo   = (const float*)d_in[4];
    float* out = (float*)d_out;

    float *qb, *ckv, *kv, *yb;
    cudaGetSymbolAddress((void**)&qb,  g_q);
    cudaGetSymbolAddress((void**)&ckv, g_ckv);
    cudaGetSymbolAddress((void**)&kv,  g_kv);
    cudaGetSymbolAddress((void**)&yb,  g_y);

    cudaFuncSetAttribute((const void*)gemm_tf32<false>,
                         cudaFuncAttributeMaxDynamicSharedMemorySize, GEMM_SMEM);
    cudaFuncSetAttribute((const void*)gemm_tf32<true>,
                         cudaFuncAttributeMaxDynamicSharedMemorySize, GEMM_SMEM);
    cudaFuncSetAttribute((const void*)mla_attn_kernel,
                         cudaFuncAttributeMaxDynamicSharedMemorySize, ATTN_SMEM);

    // 1) q = x @ Wq                       (4096 x 2048 x 2048)
    gemm_tf32<false><<<dim3(2048 / GBN, BT_ / GBM), 256, GEMM_SMEM>>>(
        x, Wq, qb, BT_, 2048, 2048, 2048, 2048, 2048);

    // 2) ckv = x @ Wkva                   (4096 x 576 x 2048)
    gemm_tf32<false><<<dim3((CKV_W + GBN - 1) / GBN, BT_ / GBM), 256, GEMM_SMEM>>>(
        x, Wkva, ckv, BT_, CKV_W, 2048, 2048, CKV_W, CKV_W);

    // 3) RoPE (in place)
    rope_q_kernel<<<(BT_ * H_ * (RD_ / 2) + 255) / 256, 256>>>(qb);
    rope_k_kernel<<<(BT_ * (RD_ / 2) + 255) / 256, 256>>>(ckv);

    // 4) kv = ckv[:, :512] @ Wkvb         (4096 x 1024 x 512), lda = 576
    gemm_tf32<false><<<dim3(KV_W / GBN, BT_ / GBM), 256, GEMM_SMEM>>>(
        ckv, Wkvb, kv, BT_, KV_W, LORA_, CKV_W, KV_W, KV_W);

    // 5) causal flash attention -> compact y (4096 x 1024)
    mla_attn_kernel<<<dim3(T_ / 64, H_, B_), 128, ATTN_SMEM>>>(qb, kv, ckv, yb);

    // 6) out = y_compact @ Wo[row-mapped] (4096 x 2048 x 1024)
    gemm_tf32<true><<<dim3(2048 / GBN, BT_ / GBM), 256, GEMM_SMEM>>>(
        yb, Wo, out, BT_, 2048, KV_W, KV_W, 2048, 2048);
}